// round 10
// baseline (speedup 1.0000x reference)
#include <cuda_runtime.h>
#include <cstdint>

#define LL    256   // sequence length
#define EE    64    // embed dim
#define GG    256   // 4H
#define NSEQ  2048  // B*S
#define NTHR  256

typedef unsigned long long u64;

// 1 GB scratch: pre[dir][n][t][j*4+g]  (input projection + bias, both directions)
__device__ float g_pre[(size_t)2 * NSEQ * LL * GG];

__device__ __forceinline__ void fma2(u64 &d, u64 a, u64 b) {
    asm("fma.rn.f32x2 %0, %1, %2, %0;" : "+l"(d) : "l"(a), "l"(b));
}
__device__ __forceinline__ u64 pack2(float lo, float hi) {
    u64 r; asm("mov.b64 %0, {%1, %2};" : "=l"(r) : "f"(lo), "f"(hi)); return r;
}
__device__ __forceinline__ float hsum2(u64 v) {
    float lo, hi; asm("mov.b64 {%0, %1}, %2;" : "=f"(lo), "=f"(hi) : "l"(v));
    return lo + hi;
}
__device__ __forceinline__ float tanha(float x) {
    float y; asm("tanh.approx.f32 %0, %1;" : "=f"(y) : "f"(x)); return y;
}
__device__ __forceinline__ void stcs4(float* p, float4 v) {
    asm volatile("st.global.cs.v4.f32 [%0], {%1,%2,%3,%4};"
                 :: "l"(p), "f"(v.x), "f"(v.y), "f"(v.z), "f"(v.w) : "memory");
}
__device__ __forceinline__ float4 ldcs4(const float* p) {
    float4 v;
    asm volatile("ld.global.cs.v4.f32 {%0,%1,%2,%3}, [%4];"
                 : "=f"(v.x), "=f"(v.y), "=f"(v.z), "=f"(v.w) : "l"(p));
    return v;
}

#define XSTRIDE 68

// fp32 weight SMEM layout (K-paired for f32x2), two arrays:
//   w0[e2*256 + j*4 + g*2 + s] = W[(2*e2+s)*GG + g*64 + j]      g in {i,f}
//   w1[e2*256 + j*4 + g*2 + s] = W[(2*e2+s)*GG + (g+2)*64 + j]  g in {g,o}
template<int NT>
__device__ __forceinline__ void load_weights(float* w0, float* w1,
                                             const float* W, int tid) {
    for (int idx = tid; idx < 8192; idx += NT) {
        int e2  = idx >> 8;
        int rem = idx & 255;
        int jj  = rem >> 2;
        int g   = (rem >> 1) & 1;
        int s   = rem & 1;
        int e   = 2 * e2 + s;
        w0[idx] = W[e * GG + g * 64 + jj];
        w1[idx] = W[e * GG + (g + 2) * 64 + jj];
    }
}

// ============================================================================
// Kernel 1: pre[dir][m][g] = embed[ids[m]] @ Wk_dir + b_dir   (m = n*LL + t)
// 256 threads = 4 independent 64-thread groups (2 warps each). Each group
// processes 8-row tiles (8 rows/thread), private double-buffered x staging,
// named barriers only -> groups drift; LDG prefetch one tile ahead.
// ============================================================================
#define K1_TILES 8
#define K1_ROWS_CTA 256          // 4 groups * 8 tiles * 8 rows
#define K1_XS_G (2 * 8 * XSTRIDE)
#define K1_SMEM_FLOATS (16384 + 4 * K1_XS_G)

__global__ void __launch_bounds__(NTHR, 1)
pre_kernel(const int* __restrict__ ids,
           const float* __restrict__ embed,
           const float* __restrict__ Wk_f, const float* __restrict__ b_f,
           const float* __restrict__ Wk_b, const float* __restrict__ b_b)
{
    extern __shared__ float smem[];
    float* wk0 = smem;
    float* wk1 = smem + 8192;

    const int tid = threadIdx.x;
    const int dir = blockIdx.y;
    const float* Wk = dir ? Wk_b : Wk_f;
    const float* bb = dir ? b_b  : b_f;

    load_weights<NTHR>(wk0, wk1, Wk, tid);

    const int j     = tid & 63;
    const int q     = tid >> 6;          // group 0..3
    const int barid = q + 1;
    float* xsg = smem + 16384 + q * K1_XS_G;   // group-private 2 x [8][68]

    // gather mapping: 8 threads per row, 8 floats each
    const int grow = j >> 3;             // local row 0..7
    const int ge   = (j & 7) * 8;        // e offset

    const float bi = bb[j], bf = bb[64 + j], bg = bb[128 + j], bo = bb[192 + j];

    const size_t m_base = (size_t)blockIdx.x * K1_ROWS_CTA + q * (K1_TILES * 8);
    const size_t dbase  = (size_t)dir * NSEQ * LL;

    __syncthreads();   // weights ready (only CTA-wide barrier)

    // prefetch tile 0
    float4 xvA, xvB;
    {
        int id = ids[m_base + grow];
        const float4* src = (const float4*)(embed + (size_t)id * EE + ge);
        xvA = src[0];
        xvB = src[1];
    }

    int buf = 0;
    for (int tile = 0; tile < K1_TILES; ++tile) {
        float* xs = xsg + buf * (8 * XSTRIDE);
        {
            float4* dst = (float4*)&xs[grow * XSTRIDE + ge];
            dst[0] = xvA;
            dst[1] = xvB;
        }
        asm volatile("bar.sync %0, %1;" :: "r"(barid), "r"(64) : "memory");

        // prefetch next tile (lands under compute)
        if (tile + 1 < K1_TILES) {
            int id = ids[m_base + (size_t)(tile + 1) * 8 + grow];
            const float4* src = (const float4*)(embed + (size_t)id * EE + ge);
            xvA = src[0];
            xvB = src[1];
        }

        u64 a0[8], a1[8], a2[8], a3[8];
#pragma unroll
        for (int p = 0; p < 8; ++p) {
            a0[p] = pack2(bi, 0.f);
            a1[p] = pack2(bf, 0.f);
            a2[p] = pack2(bg, 0.f);
            a3[p] = pack2(bo, 0.f);
        }

#pragma unroll 2
        for (int e4 = 0; e4 < 16; ++e4) {
            const ulonglong2 wA0 = *(const ulonglong2*)(wk0 + (2 * e4) * 256 + j * 4);
            const ulonglong2 wB0 = *(const ulonglong2*)(wk1 + (2 * e4) * 256 + j * 4);
            const ulonglong2 wA1 = *(const ulonglong2*)(wk0 + (2 * e4 + 1) * 256 + j * 4);
            const ulonglong2 wB1 = *(const ulonglong2*)(wk1 + (2 * e4 + 1) * 256 + j * 4);
#pragma unroll
            for (int p = 0; p < 8; ++p) {
                ulonglong2 x4 = *(const ulonglong2*)(xs + p * XSTRIDE + e4 * 4);
                fma2(a0[p], x4.x, wA0.x);
                fma2(a1[p], x4.x, wA0.y);
                fma2(a2[p], x4.x, wB0.x);
                fma2(a3[p], x4.x, wB0.y);
                fma2(a0[p], x4.y, wA1.x);
                fma2(a1[p], x4.y, wA1.y);
                fma2(a2[p], x4.y, wB1.x);
                fma2(a3[p], x4.y, wB1.y);
            }
        }

        const size_t m0 = m_base + (size_t)tile * 8;
#pragma unroll
        for (int p = 0; p < 8; ++p) {
            float4 r;
            r.x = hsum2(a0[p]);
            r.y = hsum2(a1[p]);
            r.z = hsum2(a2[p]);
            r.w = hsum2(a3[p]);
            stcs4(&g_pre[(dbase + m0 + p) * GG + j * 4], r);
        }
        buf ^= 1;
    }
}

// ============================================================================
// Kernel 2: recurrence only (h @ Wr per step). 256 threads = 4 drifting
// 64-thread groups, 8 rows/thread, double-buffered hs, pre prefetched 1 step
// ahead, fp32 weights, tanh.approx epilogue.
// ============================================================================
#define ROWS 32
#define K2_SMEM_FLOATS (16384 + 2 * (ROWS * XSTRIDE))

__global__ void __launch_bounds__(NTHR, 1)
rec_kernel(const float* __restrict__ Wr_f,
           const float* __restrict__ Wr_b,
           float* __restrict__ out)
{
    extern __shared__ float smem[];
    float* wr0   = smem;
    float* wr1   = smem + 8192;
    float* hsbuf = smem + 16384;       // 2 x [32][68]

    const int tid   = threadIdx.x;
    const int dir   = blockIdx.y;
    const int nbase = blockIdx.x * ROWS;
    const float* Wr = dir ? Wr_b : Wr_f;

    load_weights<NTHR>(wr0, wr1, Wr, tid);

    const int j  = tid & 63;
    const int q  = tid >> 6;           // group 0..3
    const int r0 = q * 8;              // 8 rows per thread, group-private
    const int barid = q + 1;

    const float* preb = g_pre + (size_t)dir * NSEQ * LL * GG;

    float c_[8], h_[8];
    float4 pv[8];
#pragma unroll
    for (int p = 0; p < 8; ++p) { c_[p] = 0.f; h_[p] = 0.f; }

    // prefetch pre for step 0
    {
        const int te0 = dir ? (LL - 1) : 0;
#pragma unroll
        for (int p = 0; p < 8; ++p)
            pv[p] = ldcs4(&preb[((size_t)(nbase + r0 + p) * LL + te0) * GG + j * 4]);
    }

    __syncthreads();   // weights ready (only CTA-wide barrier)

    int buf = 0;
    for (int t = 0; t < LL; ++t) {
        const int te = dir ? (LL - 1 - t) : t;
        float* hs = hsbuf + buf * (ROWS * XSTRIDE);

        // publish h_t (rows r0..r0+7 — read only by this 64-thread group)
#pragma unroll
        for (int p = 0; p < 8; ++p)
            hs[(r0 + p) * XSTRIDE + j] = h_[p];
        asm volatile("bar.sync %0, %1;" :: "r"(barid), "r"(64) : "memory");

        // consume prefetched pre into accumulators
        u64 a0[8], a1[8], a2[8], a3[8];
#pragma unroll
        for (int p = 0; p < 8; ++p) {
            a0[p] = pack2(pv[p].x, 0.f);
            a1[p] = pack2(pv[p].y, 0.f);
            a2[p] = pack2(pv[p].z, 0.f);
            a3[p] = pack2(pv[p].w, 0.f);
        }

        // issue prefetch for step t+1 (lands during the compute below)
        {
            const int tn = (t + 1 < LL) ? (dir ? (LL - 2 - t) : (t + 1)) : te;
#pragma unroll
            for (int p = 0; p < 8; ++p)
                pv[p] = ldcs4(&preb[((size_t)(nbase + r0 + p) * LL + tn) * GG + j * 4]);
        }

        if (t != 0) {   // h == 0 at t==0: skip the matmul
#pragma unroll 2
            for (int e4 = 0; e4 < 16; ++e4) {
                const ulonglong2 wA0 = *(const ulonglong2*)(wr0 + (2 * e4) * 256 + j * 4);
                const ulonglong2 wB0 = *(const ulonglong2*)(wr1 + (2 * e4) * 256 + j * 4);
                const ulonglong2 wA1 = *(const ulonglong2*)(wr0 + (2 * e4 + 1) * 256 + j * 4);
                const ulonglong2 wB1 = *(const ulonglong2*)(wr1 + (2 * e4 + 1) * 256 + j * 4);
#pragma unroll
                for (int p = 0; p < 8; ++p) {
                    ulonglong2 h4 = *(const ulonglong2*)(hs + (r0 + p) * XSTRIDE + e4 * 4);
                    fma2(a0[p], h4.x, wA0.x);
                    fma2(a1[p], h4.x, wA0.y);
                    fma2(a2[p], h4.x, wB0.x);
                    fma2(a3[p], h4.x, wB0.y);
                    fma2(a0[p], h4.y, wA1.x);
                    fma2(a1[p], h4.y, wA1.y);
                    fma2(a2[p], h4.y, wB1.x);
                    fma2(a3[p], h4.y, wB1.y);
                }
            }
        }

        // epilogue: HW tanh; sigmoid(x) = 0.5*tanh(0.5x) + 0.5
#pragma unroll
        for (int p = 0; p < 8; ++p) {
            float zi = hsum2(a0[p]);
            float zf = hsum2(a1[p]);
            float zg = hsum2(a2[p]);
            float zo = hsum2(a3[p]);
            float ig  = fmaf(0.5f, tanha(0.5f * zi), 0.5f);
            float fg  = fmaf(0.5f, tanha(0.5f * zf), 0.5f);
            float gg2 = tanha(zg);
            float og  = fmaf(0.5f, tanha(0.5f * zo), 0.5f);
            float c = fg * c_[p] + ig * gg2;
            c_[p] = c;
            float hv = og * tanha(c);
            h_[p] = hv;
            float* op = &out[((size_t)(nbase + r0 + p) * LL + te) * 128 + dir * 64 + j];
            asm volatile("st.global.cs.f32 [%0], %1;" :: "l"(op), "f"(hv) : "memory");
        }
        buf ^= 1;
    }
}

extern "C" void kernel_launch(void* const* d_in, const int* in_sizes, int n_in,
                              void* d_out, int out_size) {
    const int*   ids   = (const int*)  d_in[0];
    const float* embed = (const float*)d_in[1];
    const float* Wk_f  = (const float*)d_in[2];
    const float* Wr_f  = (const float*)d_in[3];
    const float* b_f   = (const float*)d_in[4];
    const float* Wk_b  = (const float*)d_in[5];
    const float* Wr_b  = (const float*)d_in[6];
    const float* b_b   = (const float*)d_in[7];
    float* out = (float*)d_out;

    static bool attr_set = false;
    if (!attr_set) {
        cudaFuncSetAttribute(pre_kernel,
                             cudaFuncAttributeMaxDynamicSharedMemorySize,
                             K1_SMEM_FLOATS * (int)sizeof(float));
        cudaFuncSetAttribute(rec_kernel,
                             cudaFuncAttributeMaxDynamicSharedMemorySize,
                             K2_SMEM_FLOATS * (int)sizeof(float));
        attr_set = true;
    }

    dim3 grid1((NSEQ * LL) / K1_ROWS_CTA, 2);   // 2048 x 2
    pre_kernel<<<grid1, NTHR, K1_SMEM_FLOATS * sizeof(float)>>>(
        ids, embed, Wk_f, b_f, Wk_b, b_b);

    dim3 grid2(NSEQ / ROWS, 2);                 // 64 x 2
    rec_kernel<<<grid2, NTHR, K2_SMEM_FLOATS * sizeof(float)>>>(
        Wr_f, Wr_b, out);
}

// round 12
// speedup vs baseline: 1.0008x; 1.0008x over previous
#include <cuda_runtime.h>
#include <cstdint>

#define LL    256   // sequence length
#define EE    64    // embed dim
#define GG    256   // 4H
#define NSEQ  2048  // B*S
#define NTHR  256

typedef unsigned long long u64;

// 1 GB scratch: pre[dir][n][t][j*4+g]  (input projection + bias, both directions)
__device__ float g_pre[(size_t)2 * NSEQ * LL * GG];

__device__ __forceinline__ void fma2(u64 &d, u64 a, u64 b) {
    asm("fma.rn.f32x2 %0, %1, %2, %0;" : "+l"(d) : "l"(a), "l"(b));
}
__device__ __forceinline__ u64 pack2(float lo, float hi) {
    u64 r; asm("mov.b64 %0, {%1, %2};" : "=l"(r) : "f"(lo), "f"(hi)); return r;
}
__device__ __forceinline__ float hsum2(u64 v) {
    float lo, hi; asm("mov.b64 {%0, %1}, %2;" : "=f"(lo), "=f"(hi) : "l"(v));
    return lo + hi;
}
__device__ __forceinline__ float tanha(float x) {
    float y; asm("tanh.approx.f32 %0, %1;" : "=f"(y) : "f"(x)); return y;
}
__device__ __forceinline__ void stcs4(float* p, float4 v) {
    asm volatile("st.global.cs.v4.f32 [%0], {%1,%2,%3,%4};"
                 :: "l"(p), "f"(v.x), "f"(v.y), "f"(v.z), "f"(v.w) : "memory");
}
__device__ __forceinline__ float4 ldcs4(const float* p) {
    float4 v;
    asm volatile("ld.global.cs.v4.f32 {%0,%1,%2,%3}, [%4];"
                 : "=f"(v.x), "=f"(v.y), "=f"(v.z), "=f"(v.w) : "l"(p));
    return v;
}

#define XSTRIDE 68

// fp32 weight SMEM layout (K-paired for f32x2), two arrays:
//   w0[e2*256 + j*4 + g*2 + s] = W[(2*e2+s)*GG + g*64 + j]      g in {i,f}
//   w1[e2*256 + j*4 + g*2 + s] = W[(2*e2+s)*GG + (g+2)*64 + j]  g in {g,o}
template<int NT>
__device__ __forceinline__ void load_weights(float* w0, float* w1,
                                             const float* W, int tid) {
    for (int idx = tid; idx < 8192; idx += NT) {
        int e2  = idx >> 8;
        int rem = idx & 255;
        int jj  = rem >> 2;
        int g   = (rem >> 1) & 1;
        int s   = rem & 1;
        int e   = 2 * e2 + s;
        w0[idx] = W[e * GG + g * 64 + jj];
        w1[idx] = W[e * GG + (g + 2) * 64 + jj];
    }
}

// ============================================================================
// Kernel 1: pre[dir][m][g] = embed[ids[m]] @ Wk_dir + b_dir   (m = n*LL + t)
// 256 threads, 2 CTAs/SM. 4 independent 64-thread groups, 4-row tiles
// (4 rows/thread), private double-buffered x staging, named barriers only.
// ============================================================================
#define K1_TILES 8
#define K1_ROWS_CTA 128          // 4 groups * 8 tiles * 4 rows
#define K1_XS_G (2 * 4 * XSTRIDE)
#define K1_SMEM_FLOATS (16384 + 4 * K1_XS_G)

__global__ void __launch_bounds__(NTHR, 2)
pre_kernel(const int* __restrict__ ids,
           const float* __restrict__ embed,
           const float* __restrict__ Wk_f, const float* __restrict__ b_f,
           const float* __restrict__ Wk_b, const float* __restrict__ b_b)
{
    extern __shared__ float smem[];
    float* wk0 = smem;
    float* wk1 = smem + 8192;

    const int tid = threadIdx.x;
    const int dir = blockIdx.y;
    const float* Wk = dir ? Wk_b : Wk_f;
    const float* bb = dir ? b_b  : b_f;

    load_weights<NTHR>(wk0, wk1, Wk, tid);

    const int j     = tid & 63;
    const int q     = tid >> 6;          // group 0..3
    const int barid = q + 1;
    float* xsg = smem + 16384 + q * K1_XS_G;   // group-private 2 x [4][68]

    // gather mapping: 16 threads per row, 4 floats each
    const int grow = j >> 4;             // local row 0..3
    const int ge   = (j & 15) * 4;       // e offset

    const float bi = bb[j], bf = bb[64 + j], bg = bb[128 + j], bo = bb[192 + j];

    const size_t m_base = (size_t)blockIdx.x * K1_ROWS_CTA + q * (K1_TILES * 4);
    const size_t dbase  = (size_t)dir * NSEQ * LL;

    __syncthreads();   // weights ready (only CTA-wide barrier)

    // prefetch tile 0
    float4 xv;
    {
        int id = ids[m_base + grow];
        xv = *(const float4*)(embed + (size_t)id * EE + ge);
    }

    int buf = 0;
    for (int tile = 0; tile < K1_TILES; ++tile) {
        float* xs = xsg + buf * (4 * XSTRIDE);
        *(float4*)&xs[grow * XSTRIDE + ge] = xv;
        asm volatile("bar.sync %0, %1;" :: "r"(barid), "r"(64) : "memory");

        // prefetch next tile (lands under compute)
        if (tile + 1 < K1_TILES) {
            int id = ids[m_base + (size_t)(tile + 1) * 4 + grow];
            xv = *(const float4*)(embed + (size_t)id * EE + ge);
        }

        u64 a0[4], a1[4], a2[4], a3[4];
#pragma unroll
        for (int p = 0; p < 4; ++p) {
            a0[p] = pack2(bi, 0.f);
            a1[p] = pack2(bf, 0.f);
            a2[p] = pack2(bg, 0.f);
            a3[p] = pack2(bo, 0.f);
        }

#pragma unroll 2
        for (int e4 = 0; e4 < 16; ++e4) {
            const ulonglong2 wA0 = *(const ulonglong2*)(wk0 + (2 * e4) * 256 + j * 4);
            const ulonglong2 wB0 = *(const ulonglong2*)(wk1 + (2 * e4) * 256 + j * 4);
            const ulonglong2 wA1 = *(const ulonglong2*)(wk0 + (2 * e4 + 1) * 256 + j * 4);
            const ulonglong2 wB1 = *(const ulonglong2*)(wk1 + (2 * e4 + 1) * 256 + j * 4);
#pragma unroll
            for (int p = 0; p < 4; ++p) {
                ulonglong2 x4 = *(const ulonglong2*)(xs + p * XSTRIDE + e4 * 4);
                fma2(a0[p], x4.x, wA0.x);
                fma2(a1[p], x4.x, wA0.y);
                fma2(a2[p], x4.x, wB0.x);
                fma2(a3[p], x4.x, wB0.y);
                fma2(a0[p], x4.y, wA1.x);
                fma2(a1[p], x4.y, wA1.y);
                fma2(a2[p], x4.y, wB1.x);
                fma2(a3[p], x4.y, wB1.y);
            }
        }

        const size_t m0 = m_base + (size_t)tile * 4;
#pragma unroll
        for (int p = 0; p < 4; ++p) {
            float4 r;
            r.x = hsum2(a0[p]);
            r.y = hsum2(a1[p]);
            r.z = hsum2(a2[p]);
            r.w = hsum2(a3[p]);
            stcs4(&g_pre[(dbase + m0 + p) * GG + j * 4], r);
        }
        buf ^= 1;
    }
}

// ============================================================================
// Kernel 2: recurrence only (h @ Wr per step). 256 threads, ROWS=16,
// 2 CTAs/SM. 4 drifting 64-thread groups, 4 rows/thread, double-buffered hs,
// pre prefetched 1 step ahead, fp32 weights, tanh.approx epilogue.
// ============================================================================
#define ROWS 16
#define K2_SMEM_FLOATS (16384 + 2 * (ROWS * XSTRIDE))

__global__ void __launch_bounds__(NTHR, 2)
rec_kernel(const float* __restrict__ Wr_f,
           const float* __restrict__ Wr_b,
           float* __restrict__ out)
{
    extern __shared__ float smem[];
    float* wr0   = smem;
    float* wr1   = smem + 8192;
    float* hsbuf = smem + 16384;       // 2 x [16][68]

    const int tid   = threadIdx.x;
    const int dir   = blockIdx.y;
    const int nbase = blockIdx.x * ROWS;
    const float* Wr = dir ? Wr_b : Wr_f;

    load_weights<NTHR>(wr0, wr1, Wr, tid);

    const int j  = tid & 63;
    const int q  = tid >> 6;           // group 0..3
    const int r0 = q * 4;              // 4 rows per thread, group-private
    const int barid = q + 1;

    const float* preb = g_pre + (size_t)dir * NSEQ * LL * GG;

    float c_[4], h_[4];
    float4 pv[4];
#pragma unroll
    for (int p = 0; p < 4; ++p) { c_[p] = 0.f; h_[p] = 0.f; }

    // prefetch pre for step 0
    {
        const int te0 = dir ? (LL - 1) : 0;
#pragma unroll
        for (int p = 0; p < 4; ++p)
            pv[p] = ldcs4(&preb[((size_t)(nbase + r0 + p) * LL + te0) * GG + j * 4]);
    }

    __syncthreads();   // weights ready (only CTA-wide barrier)

    int buf = 0;
    for (int t = 0; t < LL; ++t) {
        const int te = dir ? (LL - 1 - t) : t;
        float* hs = hsbuf + buf * (ROWS * XSTRIDE);

        // publish h_t (rows r0..r0+3 — read only by this 64-thread group)
#pragma unroll
        for (int p = 0; p < 4; ++p)
            hs[(r0 + p) * XSTRIDE + j] = h_[p];
        asm volatile("bar.sync %0, %1;" :: "r"(barid), "r"(64) : "memory");

        // consume prefetched pre into accumulators
        u64 a0[4], a1[4], a2[4], a3[4];
#pragma unroll
        for (int p = 0; p < 4; ++p) {
            a0[p] = pack2(pv[p].x, 0.f);
            a1[p] = pack2(pv[p].y, 0.f);
            a2[p] = pack2(pv[p].z, 0.f);
            a3[p] = pack2(pv[p].w, 0.f);
        }

        // issue prefetch for step t+1 (lands during the compute below)
        {
            const int tn = (t + 1 < LL) ? (dir ? (LL - 2 - t) : (t + 1)) : te;
#pragma unroll
            for (int p = 0; p < 4; ++p)
                pv[p] = ldcs4(&preb[((size_t)(nbase + r0 + p) * LL + tn) * GG + j * 4]);
        }

        if (t != 0) {   // h == 0 at t==0: skip the matmul
#pragma unroll 2
            for (int e4 = 0; e4 < 16; ++e4) {
                const ulonglong2 wA0 = *(const ulonglong2*)(wr0 + (2 * e4) * 256 + j * 4);
                const ulonglong2 wB0 = *(const ulonglong2*)(wr1 + (2 * e4) * 256 + j * 4);
                const ulonglong2 wA1 = *(const ulonglong2*)(wr0 + (2 * e4 + 1) * 256 + j * 4);
                const ulonglong2 wB1 = *(const ulonglong2*)(wr1 + (2 * e4 + 1) * 256 + j * 4);
#pragma unroll
                for (int p = 0; p < 4; ++p) {
                    ulonglong2 h4 = *(const ulonglong2*)(hs + (r0 + p) * XSTRIDE + e4 * 4);
                    fma2(a0[p], h4.x, wA0.x);
                    fma2(a1[p], h4.x, wA0.y);
                    fma2(a2[p], h4.x, wB0.x);
                    fma2(a3[p], h4.x, wB0.y);
                    fma2(a0[p], h4.y, wA1.x);
                    fma2(a1[p], h4.y, wA1.y);
                    fma2(a2[p], h4.y, wB1.x);
                    fma2(a3[p], h4.y, wB1.y);
                }
            }
        }

        // epilogue: HW tanh; sigmoid(x) = 0.5*tanh(0.5x) + 0.5
#pragma unroll
        for (int p = 0; p < 4; ++p) {
            float zi = hsum2(a0[p]);
            float zf = hsum2(a1[p]);
            float zg = hsum2(a2[p]);
            float zo = hsum2(a3[p]);
            float ig  = fmaf(0.5f, tanha(0.5f * zi), 0.5f);
            float fg  = fmaf(0.5f, tanha(0.5f * zf), 0.5f);
            float gg2 = tanha(zg);
            float og  = fmaf(0.5f, tanha(0.5f * zo), 0.5f);
            float c = fg * c_[p] + ig * gg2;
            c_[p] = c;
            float hv = og * tanha(c);
            h_[p] = hv;
            float* op = &out[((size_t)(nbase + r0 + p) * LL + te) * 128 + dir * 64 + j];
            asm volatile("st.global.cs.f32 [%0], %1;" :: "l"(op), "f"(hv) : "memory");
        }
        buf ^= 1;
    }
}

extern "C" void kernel_launch(void* const* d_in, const int* in_sizes, int n_in,
                              void* d_out, int out_size) {
    const int*   ids   = (const int*)  d_in[0];
    const float* embed = (const float*)d_in[1];
    const float* Wk_f  = (const float*)d_in[2];
    const float* Wr_f  = (const float*)d_in[3];
    const float* b_f   = (const float*)d_in[4];
    const float* Wk_b  = (const float*)d_in[5];
    const float* Wr_b  = (const float*)d_in[6];
    const float* b_b   = (const float*)d_in[7];
    float* out = (float*)d_out;

    static bool attr_set = false;
    if (!attr_set) {
        cudaFuncSetAttribute(pre_kernel,
                             cudaFuncAttributeMaxDynamicSharedMemorySize,
                             K1_SMEM_FLOATS * (int)sizeof(float));
        cudaFuncSetAttribute(rec_kernel,
                             cudaFuncAttributeMaxDynamicSharedMemorySize,
                             K2_SMEM_FLOATS * (int)sizeof(float));
        attr_set = true;
    }

    dim3 grid1((NSEQ * LL) / K1_ROWS_CTA, 2);   // 4096 x 2, 2 CTAs/SM
    pre_kernel<<<grid1, NTHR, K1_SMEM_FLOATS * sizeof(float)>>>(
        ids, embed, Wk_f, b_f, Wk_b, b_b);

    dim3 grid2(NSEQ / ROWS, 2);                 // 128 x 2 = 256 CTAs, 2/SM
    rec_kernel<<<grid2, NTHR, K2_SMEM_FLOATS * sizeof(float)>>>(
        Wr_f, Wr_b, out);
}

// round 13
// speedup vs baseline: 1.0135x; 1.0127x over previous
#include <cuda_runtime.h>
#include <cstdint>

#define LL    256   // sequence length
#define EE    64    // embed dim
#define GG    256   // 4H
#define NSEQ  2048  // B*S

typedef unsigned long long u64;

// 1 GB scratch: pre[dir][n][t][j*4+g]  (input projection + bias, both directions)
__device__ float g_pre[(size_t)2 * NSEQ * LL * GG];

__device__ __forceinline__ void fma2(u64 &d, u64 a, u64 b) {
    asm("fma.rn.f32x2 %0, %1, %2, %0;" : "+l"(d) : "l"(a), "l"(b));
}
__device__ __forceinline__ u64 pack2(float lo, float hi) {
    u64 r; asm("mov.b64 %0, {%1, %2};" : "=l"(r) : "f"(lo), "f"(hi)); return r;
}
__device__ __forceinline__ float hsum2(u64 v) {
    float lo, hi; asm("mov.b64 {%0, %1}, %2;" : "=f"(lo), "=f"(hi) : "l"(v));
    return lo + hi;
}
__device__ __forceinline__ float tanha(float x) {
    float y; asm("tanh.approx.f32 %0, %1;" : "=f"(y) : "f"(x)); return y;
}
__device__ __forceinline__ void stcs4(float* p, float4 v) {
    asm volatile("st.global.cs.v4.f32 [%0], {%1,%2,%3,%4};"
                 :: "l"(p), "f"(v.x), "f"(v.y), "f"(v.z), "f"(v.w) : "memory");
}
__device__ __forceinline__ float4 ldcs4(const float* p) {
    float4 v;
    asm volatile("ld.global.cs.v4.f32 {%0,%1,%2,%3}, [%4];"
                 : "=f"(v.x), "=f"(v.y), "=f"(v.z), "=f"(v.w) : "l"(p));
    return v;
}

#define XSTRIDE 68

// fp32 weight SMEM layout (K-paired for f32x2), two arrays:
//   w0[e2*256 + j*4 + g*2 + s] = W[(2*e2+s)*GG + g*64 + j]      g in {i,f}
//   w1[e2*256 + j*4 + g*2 + s] = W[(2*e2+s)*GG + (g+2)*64 + j]  g in {g,o}
template<int NT>
__device__ __forceinline__ void load_weights(float* w0, float* w1,
                                             const float* W, int tid) {
    for (int idx = tid; idx < 8192; idx += NT) {
        int e2  = idx >> 8;
        int rem = idx & 255;
        int jj  = rem >> 2;
        int g   = (rem >> 1) & 1;
        int s   = rem & 1;
        int e   = 2 * e2 + s;
        w0[idx] = W[e * GG + g * 64 + jj];
        w1[idx] = W[e * GG + (g + 2) * 64 + jj];
    }
}

// ============================================================================
// Kernel 1 (identical to R8 best): pre[dir][m][g] = embed[ids[m]] @ Wk + b
// 512 threads = 8 independent 64-thread groups, private double-buffered 4-row
// x tiles, named barriers only, LDG prefetch one tile ahead.
// ============================================================================
#define K1_NTHR 512
#define K1_TILES 8
#define K1_ROWS_CTA 256
#define K1_XS_G (2 * 4 * XSTRIDE)
#define K1_SMEM_FLOATS (16384 + 8 * K1_XS_G)

__global__ void __launch_bounds__(K1_NTHR, 1)
pre_kernel(const int* __restrict__ ids,
           const float* __restrict__ embed,
           const float* __restrict__ Wk_f, const float* __restrict__ b_f,
           const float* __restrict__ Wk_b, const float* __restrict__ b_b)
{
    extern __shared__ float smem[];
    float* wk0 = smem;
    float* wk1 = smem + 8192;

    const int tid = threadIdx.x;
    const int dir = blockIdx.y;
    const float* Wk = dir ? Wk_b : Wk_f;
    const float* bb = dir ? b_b  : b_f;

    load_weights<K1_NTHR>(wk0, wk1, Wk, tid);

    const int j     = tid & 63;
    const int q     = tid >> 6;          // group 0..7
    const int barid = q + 1;
    float* xsg = smem + 16384 + q * K1_XS_G;   // group-private 2 x [4][68]

    const int grow = j >> 4;             // local row 0..3
    const int ge   = (j & 15) * 4;       // e offset

    const float bi = bb[j], bf = bb[64 + j], bg = bb[128 + j], bo = bb[192 + j];

    const size_t m_base = (size_t)blockIdx.x * K1_ROWS_CTA + q * (K1_TILES * 4);
    const size_t dbase  = (size_t)dir * NSEQ * LL;

    __syncthreads();   // weights ready (only CTA-wide barrier)

    float4 xv;
    {
        int id = ids[m_base + grow];
        xv = *(const float4*)(embed + (size_t)id * EE + ge);
    }

    int buf = 0;
    for (int tile = 0; tile < K1_TILES; ++tile) {
        float* xs = xsg + buf * (4 * XSTRIDE);
        *(float4*)&xs[grow * XSTRIDE + ge] = xv;
        asm volatile("bar.sync %0, %1;" :: "r"(barid), "r"(64) : "memory");

        if (tile + 1 < K1_TILES) {
            int id = ids[m_base + (size_t)(tile + 1) * 4 + grow];
            xv = *(const float4*)(embed + (size_t)id * EE + ge);
        }

        u64 a0[4], a1[4], a2[4], a3[4];
#pragma unroll
        for (int p = 0; p < 4; ++p) {
            a0[p] = pack2(bi, 0.f);
            a1[p] = pack2(bf, 0.f);
            a2[p] = pack2(bg, 0.f);
            a3[p] = pack2(bo, 0.f);
        }

#pragma unroll 2
        for (int e4 = 0; e4 < 16; ++e4) {
            const ulonglong2 wA0 = *(const ulonglong2*)(wk0 + (2 * e4) * 256 + j * 4);
            const ulonglong2 wB0 = *(const ulonglong2*)(wk1 + (2 * e4) * 256 + j * 4);
            const ulonglong2 wA1 = *(const ulonglong2*)(wk0 + (2 * e4 + 1) * 256 + j * 4);
            const ulonglong2 wB1 = *(const ulonglong2*)(wk1 + (2 * e4 + 1) * 256 + j * 4);
#pragma unroll
            for (int p = 0; p < 4; ++p) {
                ulonglong2 x4 = *(const ulonglong2*)(xs + p * XSTRIDE + e4 * 4);
                fma2(a0[p], x4.x, wA0.x);
                fma2(a1[p], x4.x, wA0.y);
                fma2(a2[p], x4.x, wB0.x);
                fma2(a3[p], x4.x, wB0.y);
                fma2(a0[p], x4.y, wA1.x);
                fma2(a1[p], x4.y, wA1.y);
                fma2(a2[p], x4.y, wB1.x);
                fma2(a3[p], x4.y, wB1.y);
            }
        }

        const size_t m0 = m_base + (size_t)tile * 4;
#pragma unroll
        for (int p = 0; p < 4; ++p) {
            float4 r;
            r.x = hsum2(a0[p]);
            r.y = hsum2(a1[p]);
            r.z = hsum2(a2[p]);
            r.w = hsum2(a3[p]);
            stcs4(&g_pre[(dbase + m0 + p) * GG + j * 4], r);
        }
        buf ^= 1;
    }
}

// ============================================================================
// Kernel 2: recurrence only (h @ Wr per step). 256 threads, ROWS=28,
// 7 rows/thread -> grid 74 x 2 = 148 CTAs = EXACTLY one per SM.
// 4 drifting 64-thread groups, double-buffered hs, pre prefetched 1 step
// ahead, fp32 weights, tanh.approx epilogue. Tail CTA: clamped loads +
// guarded stores (garbage rows are row-independent and finite).
// ============================================================================
#define NTHR2 256
#define ROWS 28
#define RPT  7
#define NCTA_X 74     // ceil(2048/28)
#define K2_SMEM_FLOATS (16384 + 2 * (ROWS * XSTRIDE))

__global__ void __launch_bounds__(NTHR2)
rec_kernel(const float* __restrict__ Wr_f,
           const float* __restrict__ Wr_b,
           float* __restrict__ out)
{
    extern __shared__ float smem[];
    float* wr0   = smem;
    float* wr1   = smem + 8192;
    float* hsbuf = smem + 16384;       // 2 x [28][68]

    const int tid   = threadIdx.x;
    const int dir   = blockIdx.y;
    const int nbase = blockIdx.x * ROWS;
    const float* Wr = dir ? Wr_b : Wr_f;

    load_weights<NTHR2>(wr0, wr1, Wr, tid);

    const int j  = tid & 63;
    const int q  = tid >> 6;           // group 0..3
    const int r0 = q * RPT;            // 7 rows per thread, group-private
    const int barid = q + 1;

    const float* preb = g_pre + (size_t)dir * NSEQ * LL * GG;

    float c_[RPT], h_[RPT];
    float4 pv[RPT];
    int rowc[RPT];                     // clamped global row (for loads)
    bool rowok[RPT];                   // store guard
#pragma unroll
    for (int p = 0; p < RPT; ++p) {
        c_[p] = 0.f; h_[p] = 0.f;
        int r = nbase + r0 + p;
        rowok[p] = (r < NSEQ);
        rowc[p]  = rowok[p] ? r : (NSEQ - 1);
    }

    // prefetch pre for step 0
    {
        const int te0 = dir ? (LL - 1) : 0;
#pragma unroll
        for (int p = 0; p < RPT; ++p)
            pv[p] = ldcs4(&preb[((size_t)rowc[p] * LL + te0) * GG + j * 4]);
    }

    __syncthreads();   // weights ready (only CTA-wide barrier)

    int buf = 0;
    for (int t = 0; t < LL; ++t) {
        const int te = dir ? (LL - 1 - t) : t;
        float* hs = hsbuf + buf * (ROWS * XSTRIDE);

        // publish h_t (rows r0..r0+6 — read only by this 64-thread group)
#pragma unroll
        for (int p = 0; p < RPT; ++p)
            hs[(r0 + p) * XSTRIDE + j] = h_[p];
        asm volatile("bar.sync %0, %1;" :: "r"(barid), "r"(64) : "memory");

        // consume prefetched pre into accumulators
        u64 a0[RPT], a1[RPT], a2[RPT], a3[RPT];
#pragma unroll
        for (int p = 0; p < RPT; ++p) {
            a0[p] = pack2(pv[p].x, 0.f);
            a1[p] = pack2(pv[p].y, 0.f);
            a2[p] = pack2(pv[p].z, 0.f);
            a3[p] = pack2(pv[p].w, 0.f);
        }

        // issue prefetch for step t+1 (lands during the compute below)
        {
            const int tn = (t + 1 < LL) ? (dir ? (LL - 2 - t) : (t + 1)) : te;
#pragma unroll
            for (int p = 0; p < RPT; ++p)
                pv[p] = ldcs4(&preb[((size_t)rowc[p] * LL + tn) * GG + j * 4]);
        }

        if (t != 0) {   // h == 0 at t==0: skip the matmul
#pragma unroll 4
            for (int e4 = 0; e4 < 16; ++e4) {
                const ulonglong2 wA0 = *(const ulonglong2*)(wr0 + (2 * e4) * 256 + j * 4);
                const ulonglong2 wB0 = *(const ulonglong2*)(wr1 + (2 * e4) * 256 + j * 4);
                const ulonglong2 wA1 = *(const ulonglong2*)(wr0 + (2 * e4 + 1) * 256 + j * 4);
                const ulonglong2 wB1 = *(const ulonglong2*)(wr1 + (2 * e4 + 1) * 256 + j * 4);
#pragma unroll
                for (int p = 0; p < RPT; ++p) {
                    ulonglong2 h4 = *(const ulonglong2*)(hs + (r0 + p) * XSTRIDE + e4 * 4);
                    fma2(a0[p], h4.x, wA0.x);
                    fma2(a1[p], h4.x, wA0.y);
                    fma2(a2[p], h4.x, wB0.x);
                    fma2(a3[p], h4.x, wB0.y);
                    fma2(a0[p], h4.y, wA1.x);
                    fma2(a1[p], h4.y, wA1.y);
                    fma2(a2[p], h4.y, wB1.x);
                    fma2(a3[p], h4.y, wB1.y);
                }
            }
        }

        // epilogue: HW tanh; sigmoid(x) = 0.5*tanh(0.5x) + 0.5
#pragma unroll
        for (int p = 0; p < RPT; ++p) {
            float zi = hsum2(a0[p]);
            float zf = hsum2(a1[p]);
            float zg = hsum2(a2[p]);
            float zo = hsum2(a3[p]);
            float ig  = fmaf(0.5f, tanha(0.5f * zi), 0.5f);
            float fg  = fmaf(0.5f, tanha(0.5f * zf), 0.5f);
            float gg2 = tanha(zg);
            float og  = fmaf(0.5f, tanha(0.5f * zo), 0.5f);
            float c = fg * c_[p] + ig * gg2;
            c_[p] = c;
            float hv = og * tanha(c);
            h_[p] = hv;
            if (rowok[p]) {
                float* op = &out[((size_t)(nbase + r0 + p) * LL + te) * 128 + dir * 64 + j];
                asm volatile("st.global.cs.f32 [%0], %1;" :: "l"(op), "f"(hv) : "memory");
            }
        }
        buf ^= 1;
    }
}

extern "C" void kernel_launch(void* const* d_in, const int* in_sizes, int n_in,
                              void* d_out, int out_size) {
    const int*   ids   = (const int*)  d_in[0];
    const float* embed = (const float*)d_in[1];
    const float* Wk_f  = (const float*)d_in[2];
    const float* Wr_f  = (const float*)d_in[3];
    const float* b_f   = (const float*)d_in[4];
    const float* Wk_b  = (const float*)d_in[5];
    const float* Wr_b  = (const float*)d_in[6];
    const float* b_b   = (const float*)d_in[7];
    float* out = (float*)d_out;

    static bool attr_set = false;
    if (!attr_set) {
        cudaFuncSetAttribute(pre_kernel,
                             cudaFuncAttributeMaxDynamicSharedMemorySize,
                             K1_SMEM_FLOATS * (int)sizeof(float));
        cudaFuncSetAttribute(rec_kernel,
                             cudaFuncAttributeMaxDynamicSharedMemorySize,
                             K2_SMEM_FLOATS * (int)sizeof(float));
        attr_set = true;
    }

    dim3 grid1((NSEQ * LL) / K1_ROWS_CTA, 2);   // 2048 x 2
    pre_kernel<<<grid1, K1_NTHR, K1_SMEM_FLOATS * sizeof(float)>>>(
        ids, embed, Wk_f, b_f, Wk_b, b_b);

    dim3 grid2(NCTA_X, 2);                      // 74 x 2 = 148 CTAs, 1/SM
    rec_kernel<<<grid2, NTHR2, K2_SMEM_FLOATS * sizeof(float)>>>(
        Wr_f, Wr_b, out);
}

// round 14
// speedup vs baseline: 2.0979x; 2.0699x over previous
#include <cuda_runtime.h>
#include <cstdint>

#define LL    256   // sequence length
#define EE    64    // embed dim
#define GG    256   // 4H
#define NSEQ  2048  // B*S
#define VV    6000  // vocab
#define VCAP  6016  // padded vocab rows in table

typedef unsigned long long u64;

// 12.3 MB scratch: T[dir][v][j*4+g] = embed[v] @ Wk_dir + b_dir  (L2-resident)
__device__ float g_tab[(size_t)2 * VCAP * GG];

__device__ __forceinline__ void fma2(u64 &d, u64 a, u64 b) {
    asm("fma.rn.f32x2 %0, %1, %2, %0;" : "+l"(d) : "l"(a), "l"(b));
}
__device__ __forceinline__ u64 pack2(float lo, float hi) {
    u64 r; asm("mov.b64 %0, {%1, %2};" : "=l"(r) : "f"(lo), "f"(hi)); return r;
}
__device__ __forceinline__ float hsum2(u64 v) {
    float lo, hi; asm("mov.b64 {%0, %1}, %2;" : "=f"(lo), "=f"(hi) : "l"(v));
    return lo + hi;
}
__device__ __forceinline__ float tanha(float x) {
    float y; asm("tanh.approx.f32 %0, %1;" : "=f"(y) : "f"(x)); return y;
}

#define XSTRIDE 68

// fp32 weight SMEM layout (K-paired for f32x2), two arrays:
//   w0[e2*256 + j*4 + g*2 + s] = W[(2*e2+s)*GG + g*64 + j]      g in {i,f}
//   w1[e2*256 + j*4 + g*2 + s] = W[(2*e2+s)*GG + (g+2)*64 + j]  g in {g,o}
template<int NT>
__device__ __forceinline__ void load_weights(float* w0, float* w1,
                                             const float* W, int tid) {
    for (int idx = tid; idx < 8192; idx += NT) {
        int e2  = idx >> 8;
        int rem = idx & 255;
        int jj  = rem >> 2;
        int g   = (rem >> 1) & 1;
        int s   = rem & 1;
        int e   = 2 * e2 + s;
        w0[idx] = W[e * GG + g * 64 + jj];
        w1[idx] = W[e * GG + (g + 2) * 64 + jj];
    }
}

// ============================================================================
// Kernel 1: vocab table T[dir][v][g] = embed[v] @ Wk_dir + b_dir, v < 6000.
// 256 threads = 4 drifting 64-thread groups, 4 rows/thread-tile, 8 tiles.
// grid (47, 2): 47*128 = 6016 rows (clamped loads, guarded stores).
// ============================================================================
#define K1_NTHR 256
#define K1_TILES 8
#define K1_ROWS_CTA 128          // 4 groups * 8 tiles * 4 rows
#define K1_XS_G (2 * 4 * XSTRIDE)
#define K1_SMEM_FLOATS (16384 + 4 * K1_XS_G)

__global__ void __launch_bounds__(K1_NTHR, 1)
tab_kernel(const float* __restrict__ embed,
           const float* __restrict__ Wk_f, const float* __restrict__ b_f,
           const float* __restrict__ Wk_b, const float* __restrict__ b_b)
{
    extern __shared__ float smem[];
    float* wk0 = smem;
    float* wk1 = smem + 8192;

    const int tid = threadIdx.x;
    const int dir = blockIdx.y;
    const float* Wk = dir ? Wk_b : Wk_f;
    const float* bb = dir ? b_b  : b_f;

    load_weights<K1_NTHR>(wk0, wk1, Wk, tid);

    const int j     = tid & 63;
    const int q     = tid >> 6;          // group 0..3
    const int barid = q + 1;
    float* xsg = smem + 16384 + q * K1_XS_G;   // group-private 2 x [4][68]

    const int grow = j >> 4;             // local row 0..3
    const int ge   = (j & 15) * 4;       // e offset

    const float bi = bb[j], bf = bb[64 + j], bg = bb[128 + j], bo = bb[192 + j];

    const int v_base = blockIdx.x * K1_ROWS_CTA + q * (K1_TILES * 4);
    float* tb = g_tab + (size_t)dir * VCAP * GG;

    __syncthreads();   // weights ready (only CTA-wide barrier)

    // prefetch tile 0 (clamped)
    float4 xv;
    {
        int v = v_base + grow; if (v >= VV) v = VV - 1;
        xv = *(const float4*)(embed + (size_t)v * EE + ge);
    }

    int buf = 0;
    for (int tile = 0; tile < K1_TILES; ++tile) {
        float* xs = xsg + buf * (4 * XSTRIDE);
        *(float4*)&xs[grow * XSTRIDE + ge] = xv;
        asm volatile("bar.sync %0, %1;" :: "r"(barid), "r"(64) : "memory");

        if (tile + 1 < K1_TILES) {
            int v = v_base + (tile + 1) * 4 + grow; if (v >= VV) v = VV - 1;
            xv = *(const float4*)(embed + (size_t)v * EE + ge);
        }

        u64 a0[4], a1[4], a2[4], a3[4];
#pragma unroll
        for (int p = 0; p < 4; ++p) {
            a0[p] = pack2(bi, 0.f);
            a1[p] = pack2(bf, 0.f);
            a2[p] = pack2(bg, 0.f);
            a3[p] = pack2(bo, 0.f);
        }

#pragma unroll 2
        for (int e4 = 0; e4 < 16; ++e4) {
            const ulonglong2 wA0 = *(const ulonglong2*)(wk0 + (2 * e4) * 256 + j * 4);
            const ulonglong2 wB0 = *(const ulonglong2*)(wk1 + (2 * e4) * 256 + j * 4);
            const ulonglong2 wA1 = *(const ulonglong2*)(wk0 + (2 * e4 + 1) * 256 + j * 4);
            const ulonglong2 wB1 = *(const ulonglong2*)(wk1 + (2 * e4 + 1) * 256 + j * 4);
#pragma unroll
            for (int p = 0; p < 4; ++p) {
                ulonglong2 x4 = *(const ulonglong2*)(xs + p * XSTRIDE + e4 * 4);
                fma2(a0[p], x4.x, wA0.x);
                fma2(a1[p], x4.x, wA0.y);
                fma2(a2[p], x4.x, wB0.x);
                fma2(a3[p], x4.x, wB0.y);
                fma2(a0[p], x4.y, wA1.x);
                fma2(a1[p], x4.y, wA1.y);
                fma2(a2[p], x4.y, wB1.x);
                fma2(a3[p], x4.y, wB1.y);
            }
        }

#pragma unroll
        for (int p = 0; p < 4; ++p) {
            int v = v_base + tile * 4 + p;
            if (v < VV) {
                float4 r;
                r.x = hsum2(a0[p]);
                r.y = hsum2(a1[p]);
                r.z = hsum2(a2[p]);
                r.w = hsum2(a3[p]);
                *(float4*)&tb[(size_t)v * GG + j * 4] = r;
            }
        }
        buf ^= 1;
    }
}

// ============================================================================
// Kernel 2: recurrence (h @ Wr per step). 256 threads, ROWS=28, 7 rows/thread
// -> grid 74 x 2 = 148 CTAs = one per SM. 4 drifting 64-thread groups,
// double-buffered hs, gate preactivations gathered one step ahead from the
// L2-resident vocab table (ids staged in SMEM). fp32 weights, tanh.approx.
// ============================================================================
#define NTHR2 256
#define ROWS 28
#define RPT  7
#define NCTA_X 74     // ceil(2048/28)
#define OFF_HS  16384
#define OFF_IDS (16384 + 2 * (ROWS * XSTRIDE))
#define K2_SMEM_FLOATS (OFF_IDS + ROWS * LL)

__global__ void __launch_bounds__(NTHR2)
rec_kernel(const int* __restrict__ ids,
           const float* __restrict__ Wr_f,
           const float* __restrict__ Wr_b,
           float* __restrict__ out)
{
    extern __shared__ float smem[];
    float* wr0   = smem;
    float* wr1   = smem + 8192;
    float* hsbuf = smem + OFF_HS;            // 2 x [28][68]
    int*   idss  = (int*)(smem + OFF_IDS);   // [28][256]

    const int tid   = threadIdx.x;
    const int dir   = blockIdx.y;
    const int nbase = blockIdx.x * ROWS;
    const float* Wr = dir ? Wr_b : Wr_f;

    load_weights<NTHR2>(wr0, wr1, Wr, tid);

    // stage this CTA's ids (clamped rows for the tail CTA)
    for (int idx = tid; idx < ROWS * LL; idx += NTHR2) {
        int lr = idx / LL;
        int gr = nbase + lr; if (gr >= NSEQ) gr = NSEQ - 1;
        idss[idx] = ids[(size_t)gr * LL + (idx % LL)];
    }

    const int j  = tid & 63;
    const int q  = tid >> 6;           // group 0..3
    const int r0 = q * RPT;            // 7 rows per thread, group-private
    const int barid = q + 1;

    const float* tb = g_tab + (size_t)dir * VCAP * GG;

    float c_[RPT], h_[RPT];
    float4 pv[RPT];
    bool rowok[RPT];
#pragma unroll
    for (int p = 0; p < RPT; ++p) {
        c_[p] = 0.f; h_[p] = 0.f;
        rowok[p] = (nbase + r0 + p < NSEQ);
    }

    __syncthreads();   // weights + ids ready (only CTA-wide barrier)

    // prefetch gate preactivations for step 0 from the vocab table
    {
        const int te0 = dir ? (LL - 1) : 0;
#pragma unroll
        for (int p = 0; p < RPT; ++p) {
            int id = idss[(r0 + p) * LL + te0];
            pv[p] = *(const float4*)&tb[(size_t)id * GG + j * 4];
        }
    }

    int buf = 0;
    for (int t = 0; t < LL; ++t) {
        const int te = dir ? (LL - 1 - t) : t;
        float* hs = hsbuf + buf * (ROWS * XSTRIDE);

        // publish h_t (rows r0..r0+6 — read only by this 64-thread group)
#pragma unroll
        for (int p = 0; p < RPT; ++p)
            hs[(r0 + p) * XSTRIDE + j] = h_[p];
        asm volatile("bar.sync %0, %1;" :: "r"(barid), "r"(64) : "memory");

        // consume prefetched preactivations into accumulators
        u64 a0[RPT], a1[RPT], a2[RPT], a3[RPT];
#pragma unroll
        for (int p = 0; p < RPT; ++p) {
            a0[p] = pack2(pv[p].x, 0.f);
            a1[p] = pack2(pv[p].y, 0.f);
            a2[p] = pack2(pv[p].z, 0.f);
            a3[p] = pack2(pv[p].w, 0.f);
        }

        // issue table gather for step t+1 (L2 hit, lands under compute)
        {
            const int tn = (t + 1 < LL) ? (dir ? (LL - 2 - t) : (t + 1)) : te;
#pragma unroll
            for (int p = 0; p < RPT; ++p) {
                int id = idss[(r0 + p) * LL + tn];
                pv[p] = *(const float4*)&tb[(size_t)id * GG + j * 4];
            }
        }

        if (t != 0) {   // h == 0 at t==0: skip the matmul
#pragma unroll 4
            for (int e4 = 0; e4 < 16; ++e4) {
                const ulonglong2 wA0 = *(const ulonglong2*)(wr0 + (2 * e4) * 256 + j * 4);
                const ulonglong2 wB0 = *(const ulonglong2*)(wr1 + (2 * e4) * 256 + j * 4);
                const ulonglong2 wA1 = *(const ulonglong2*)(wr0 + (2 * e4 + 1) * 256 + j * 4);
                const ulonglong2 wB1 = *(const ulonglong2*)(wr1 + (2 * e4 + 1) * 256 + j * 4);
#pragma unroll
                for (int p = 0; p < RPT; ++p) {
                    ulonglong2 h4 = *(const ulonglong2*)(hs + (r0 + p) * XSTRIDE + e4 * 4);
                    fma2(a0[p], h4.x, wA0.x);
                    fma2(a1[p], h4.x, wA0.y);
                    fma2(a2[p], h4.x, wB0.x);
                    fma2(a3[p], h4.x, wB0.y);
                    fma2(a0[p], h4.y, wA1.x);
                    fma2(a1[p], h4.y, wA1.y);
                    fma2(a2[p], h4.y, wB1.x);
                    fma2(a3[p], h4.y, wB1.y);
                }
            }
        }

        // epilogue: HW tanh; sigmoid(x) = 0.5*tanh(0.5x) + 0.5
#pragma unroll
        for (int p = 0; p < RPT; ++p) {
            float zi = hsum2(a0[p]);
            float zf = hsum2(a1[p]);
            float zg = hsum2(a2[p]);
            float zo = hsum2(a3[p]);
            float ig  = fmaf(0.5f, tanha(0.5f * zi), 0.5f);
            float fg  = fmaf(0.5f, tanha(0.5f * zf), 0.5f);
            float gg2 = tanha(zg);
            float og  = fmaf(0.5f, tanha(0.5f * zo), 0.5f);
            float c = fg * c_[p] + ig * gg2;
            c_[p] = c;
            float hv = og * tanha(c);
            h_[p] = hv;
            if (rowok[p]) {
                float* op = &out[((size_t)(nbase + r0 + p) * LL + te) * 128 + dir * 64 + j];
                asm volatile("st.global.cs.f32 [%0], %1;" :: "l"(op), "f"(hv) : "memory");
            }
        }
        buf ^= 1;
    }
}

extern "C" void kernel_launch(void* const* d_in, const int* in_sizes, int n_in,
                              void* d_out, int out_size) {
    const int*   ids   = (const int*)  d_in[0];
    const float* embed = (const float*)d_in[1];
    const float* Wk_f  = (const float*)d_in[2];
    const float* Wr_f  = (const float*)d_in[3];
    const float* b_f   = (const float*)d_in[4];
    const float* Wk_b  = (const float*)d_in[5];
    const float* Wr_b  = (const float*)d_in[6];
    const float* b_b   = (const float*)d_in[7];
    float* out = (float*)d_out;

    static bool attr_set = false;
    if (!attr_set) {
        cudaFuncSetAttribute(tab_kernel,
                             cudaFuncAttributeMaxDynamicSharedMemorySize,
                             K1_SMEM_FLOATS * (int)sizeof(float));
        cudaFuncSetAttribute(rec_kernel,
                             cudaFuncAttributeMaxDynamicSharedMemorySize,
                             K2_SMEM_FLOATS * (int)sizeof(float));
        attr_set = true;
    }

    dim3 grid1((VCAP + K1_ROWS_CTA - 1) / K1_ROWS_CTA, 2);   // 47 x 2
    tab_kernel<<<grid1, K1_NTHR, K1_SMEM_FLOATS * sizeof(float)>>>(
        embed, Wk_f, b_f, Wk_b, b_b);

    dim3 grid2(NCTA_X, 2);                                    // 74 x 2 = 148 CTAs
    rec_kernel<<<grid2, NTHR2, K2_SMEM_FLOATS * sizeof(float)>>>(
        ids, Wr_f, Wr_b, out);
}